// round 6
// baseline (speedup 1.0000x reference)
#include <cuda_runtime.h>

#define MD   96
#define MN   9216
#define NS   32
#define PD   52    // pitch for direct (float4-stored) smem operands
#define PT   49    // pitch for transpose-stored smem operands (odd -> 3-way STS max)
#define SMSZ 5044  // 97 * 52 floats (covers 97*49 too)

// scratch (device globals; allocation is forbidden)
__device__ float g_LM [MN];
__device__ float g_LN [MN];
__device__ float g_Gy [NS * MN];   // [s][p][nu]
__device__ float g_GxP[NS * MN];   // [t][q][mm]
__device__ float g_HP [NS * MN];   // [t][nn][mm]
__device__ float g_PT [NS * MN];   // [t][mm][nn]  (transposed P)

__device__ __forceinline__ float wrapf(float v) {
    float r = fmodf(v + 1.0f, 2.0f);
    if (r < 0.0f) r += 2.0f;
    return r - 1.0f;
}

// S[k*P + j] = g[k*96 + colbase + j], k<96, j<48  (both sides float4)
template<int P>
__device__ __forceinline__ void load_direct(float* S, const float* __restrict__ g,
                                            int colbase, int tid) {
    for (int idx = tid; idx < 96 * 12; idx += 128) {
        int k = idx / 12, j4 = idx % 12;
        float4 v = *(const float4*)(g + k * MD + colbase + 4 * j4);
        *(float4*)(S + k * P + 4 * j4) = v;
    }
}

// S[k*P + i] = g[(rowbase+i)*96 + k]  (coalesced global read, scattered STS)
template<int P>
__device__ __forceinline__ void load_trans(float* S, const float* __restrict__ g,
                                           int rowbase, int tid) {
    for (int idx = tid; idx < 48 * 24; idx += 128) {
        int i = idx / 24, k4 = idx % 24;
        float4 v = *(const float4*)(g + (rowbase + i) * MD + 4 * k4);
        S[(4 * k4 + 0) * P + i] = v.x;
        S[(4 * k4 + 1) * P + i] = v.y;
        S[(4 * k4 + 2) * P + i] = v.z;
        S[(4 * k4 + 3) * P + i] = v.w;
    }
}

// 6x3 register-tile matmul over K=96, double-buffered operand prefetch.
template<int PA, int PB>
__device__ __forceinline__ void mm6x3(const float* SA, const float* SB,
                                      float acc[6][3], int r0, int c0) {
    float a0[6], b0[3], a1[6], b1[3];
#pragma unroll
    for (int d = 0; d < 6; d++) a0[d] = SA[0 * PA + r0 + d];
#pragma unroll
    for (int d = 0; d < 3; d++) b0[d] = SB[0 * PB + c0 + d];
    for (int k = 0; k < 96; k += 2) {
#pragma unroll
        for (int d = 0; d < 6; d++) a1[d] = SA[(k + 1) * PA + r0 + d];
#pragma unroll
        for (int d = 0; d < 3; d++) b1[d] = SB[(k + 1) * PB + c0 + d];
#pragma unroll
        for (int i = 0; i < 6; i++)
#pragma unroll
            for (int j = 0; j < 3; j++) acc[i][j] += a0[i] * b0[j];
#pragma unroll
        for (int d = 0; d < 6; d++) a0[d] = SA[(k + 2) * PA + r0 + d];  // row 96 pad
#pragma unroll
        for (int d = 0; d < 3; d++) b0[d] = SB[(k + 2) * PB + c0 + d];
#pragma unroll
        for (int i = 0; i < 6; i++)
#pragma unroll
            for (int j = 0; j < 3; j++) acc[i][j] += a1[i] * b1[j];
    }
}

// stage acc tile in smem (pitch 49), then scatter columns nu -> (t,e) coalesced:
// dst[t*MN + (s+32e)*96 + rb + row] = T[col][row]
__device__ __forceinline__ void scatter_perm(float* Ts, float* __restrict__ dst,
                                             const float acc[6][3], int wrap_it,
                                             int s, int rb, int cb,
                                             int r0, int c0, int tid) {
#pragma unroll
    for (int i = 0; i < 6; i++)
#pragma unroll
        for (int j = 0; j < 3; j++)
            Ts[(c0 + j) * 49 + r0 + i] = wrap_it ? wrapf(acc[i][j]) : acc[i][j];
    __syncthreads();
    for (int idx = tid; idx < 48 * 48; idx += 128) {
        int col = idx / 48, row = idx % 48;
        int nu = cb + col;
        int t = nu / 3, e = nu - 3 * t;
        dst[t * MN + (s + 32 * e) * MD + rb + row] = Ts[col * 49 + row];
    }
}

// ---------------------------------------------------------------------------
// S1: grid 264.  b<8: gram.  b in [8,264): diffs Gy / GxP.
// ---------------------------------------------------------------------------
__global__ __launch_bounds__(128) void s1_gram_diffs(const float* __restrict__ x,
                                                     const float* __restrict__ DM,
                                                     const float* __restrict__ DN) {
    __shared__ float SA[SMSZ];
    __shared__ float SB[SMSZ];
    int tid = threadIdx.x;
    int tx = tid & 15, ty = tid >> 4;
    int r0 = 6 * ty, c0 = 3 * tx;
    float acc[6][3] = {};
    int b = blockIdx.x;
    if (b < 8) {
        int mat = b >> 2, tile = b & 3;
        int rb = (tile >> 1) * 48, cb = (tile & 1) * 48;
        const float* D = mat ? DN : DM;
        float* O = mat ? g_LN : g_LM;
        load_direct<PD>(SA, D, rb, tid);    // As[k][i] = D[k][rb+i] (=D^T col)
        load_direct<PD>(SB, D, cb, tid);
        __syncthreads();
        mm6x3<PD, PD>(SA, SB, acc, r0, c0);
#pragma unroll
        for (int i = 0; i < 6; i++)
#pragma unroll
            for (int j = 0; j < 3; j++)
                O[(rb + r0 + i) * MD + cb + c0 + j] = acc[i][j];
    } else {
        int idx2 = b - 8;
        int s = idx2 >> 3, sub = idx2 & 7;
        int which = sub >> 2, tile = sub & 3;
        int rb = (tile >> 1) * 48, cb = (tile & 1) * 48;
        const float* Xs = x + s * MN;
        if (which == 0) {   // Gy[p][nu] = sum_mi DM[p][mi] Xs[mi][nu]
            load_trans<PT>(SA, DM, rb, tid);
            load_direct<PD>(SB, Xs, cb, tid);
            __syncthreads();
            mm6x3<PT, PD>(SA, SB, acc, r0, c0);
#pragma unroll
            for (int i = 0; i < 6; i++)
#pragma unroll
                for (int j = 0; j < 3; j++)
                    g_Gy[s * MN + (rb + r0 + i) * MD + cb + c0 + j] = wrapf(acc[i][j]);
        } else {            // Gx[mi][q] = sum_ni Xs[mi][ni] DN[q][ni] -> GxP[t][q][mm]
            load_trans<PT>(SA, Xs, rb, tid);
            load_trans<PT>(SB, DN, cb, tid);
            __syncthreads();
            mm6x3<PT, PT>(SA, SB, acc, r0, c0);
            __syncthreads();
            scatter_perm(SB, g_GxP, acc, 1, s, rb, cb, r0, c0, tid);
        }
    }
}

// ---------------------------------------------------------------------------
// S2: grid 128.  H[mm][nu] = sum_p DM[p][mm] Gy[s][p][nu]  -> HP[t][nn][mm]
// ---------------------------------------------------------------------------
__global__ __launch_bounds__(128) void s2_H(const float* __restrict__ DM) {
    __shared__ float SA[SMSZ];
    __shared__ float SB[SMSZ];
    int tid = threadIdx.x;
    int tx = tid & 15, ty = tid >> 4;
    int r0 = 6 * ty, c0 = 3 * tx;
    int s = blockIdx.x >> 2, tile = blockIdx.x & 3;
    int rb = (tile >> 1) * 48, cb = (tile & 1) * 48;
    load_direct<PD>(SA, DM, rb, tid);                // As[k][i] = DM[k][rb+i]
    load_direct<PD>(SB, g_Gy + s * MN, cb, tid);
    __syncthreads();
    float acc[6][3] = {};
    mm6x3<PD, PD>(SA, SB, acc, r0, c0);
    __syncthreads();
    scatter_perm(SB, g_HP, acc, 0, s, rb, cb, r0, c0, tid);
}

// ---------------------------------------------------------------------------
// S3: grid 128.  PT[t][mm][nn] = sum_q GxP[t][q][mm] DN[q][nn]
//                              + HP[t][nn][mm] + eta*x[s2][mm][nn]
// ---------------------------------------------------------------------------
__global__ __launch_bounds__(128) void s3_P(const float* __restrict__ x,
                                            const float* __restrict__ DN,
                                            const float* __restrict__ eta) {
    __shared__ float SA[SMSZ];
    __shared__ float SB[SMSZ];
    int tid = threadIdx.x;
    int tx = tid & 15, ty = tid >> 4;
    int r0 = 6 * ty, c0 = 3 * tx;
    int t = blockIdx.x >> 2, tile = blockIdx.x & 3;
    int rb = (tile >> 1) * 48, cb = (tile & 1) * 48;   // rb: mm rows, cb: nn cols
    int s2 = 4 * (t & 7) + (t >> 3);
    load_direct<PD>(SA, g_GxP + t * MN, rb, tid);    // As[q][i] = GxP[t][q][rb+i]
    load_direct<PD>(SB, DN, cb, tid);                // Bs[q][j] = DN[q][cb+j]
    __syncthreads();
    float acc[6][3] = {};
    mm6x3<PD, PD>(SA, SB, acc, r0, c0);
    __syncthreads();
    // stage HP tile transposed: Ts[jj][ii] = HP[t][cb+jj][rb+ii]  (coalesced read)
    for (int idx = tid; idx < 48 * 48; idx += 128) {
        int jj = idx / 48, ii = idx % 48;
        SB[jj * 49 + ii] = g_HP[t * MN + (cb + jj) * MD + rb + ii];
    }
    __syncthreads();
    float ev = eta[0];
#pragma unroll
    for (int i = 0; i < 6; i++)
#pragma unroll
        for (int j = 0; j < 3; j++) {
            float v = acc[i][j]
                    + SB[(c0 + j) * 49 + r0 + i]
                    + ev * x[s2 * MN + (rb + r0 + i) * MD + cb + c0 + j];
            g_PT[t * MN + (rb + r0 + i) * MD + cb + c0 + j] = v;
        }
}

// ---------------------------------------------------------------------------
// S4: grid 128.  out[s2] = LM@PT + PT@LN + eta*PT   (LM, LN symmetric)
// ---------------------------------------------------------------------------
__global__ __launch_bounds__(128) void s4_out(const float* __restrict__ eta,
                                              float* __restrict__ out) {
    __shared__ float SA[SMSZ];
    __shared__ float SB[SMSZ];
    int tid = threadIdx.x;
    int tx = tid & 15, ty = tid >> 4;
    int r0 = 6 * ty, c0 = 3 * tx;
    int t = blockIdx.x >> 2, tile = blockIdx.x & 3;
    int rb = (tile >> 1) * 48, cb = (tile & 1) * 48;
    int s2 = 4 * (t & 7) + (t >> 3);
    const float* Pt = g_PT + t * MN;
    float acc[6][3] = {};

    // phase 1: LM @ PT  (LM symmetric -> direct load)
    load_direct<PD>(SA, g_LM, rb, tid);              // As[k][i] = LM[k][rb+i] = LM[rb+i][k]
    load_direct<PD>(SB, Pt, cb, tid);                // Bs[k][j] = PT[k][cb+j]
    __syncthreads();
    mm6x3<PD, PD>(SA, SB, acc, r0, c0);
    __syncthreads();

    // phase 2: PT @ LN
    load_trans<PT>(SA, Pt, rb, tid);                 // As[k][i] = PT[rb+i][k]
    load_direct<PD>(SB, g_LN, cb, tid);              // Bs[k][j] = LN[k][cb+j]
    __syncthreads();
    mm6x3<PT, PD>(SA, SB, acc, r0, c0);

    float ev = eta[0];
#pragma unroll
    for (int i = 0; i < 6; i++)
#pragma unroll
        for (int j = 0; j < 3; j++) {
            int off = (rb + r0 + i) * MD + cb + c0 + j;
            out[s2 * MN + off] = acc[i][j] + ev * Pt[off];
        }
}

// ---------------------------------------------------------------------------
extern "C" void kernel_launch(void* const* d_in, const int* in_sizes, int n_in,
                              void* d_out, int out_size) {
    // inputs: x(294912), eta(1), A_w(84934656, unused), DM(9216), DN(9216)
    int ix = 0, ie = 1, idm = 3, idn = 4;
    {
        int found_d = 0;
        for (int i = 0; i < n_in; i++) {
            if (in_sizes[i] == 294912) ix = i;
            else if (in_sizes[i] == 1) ie = i;
            else if (in_sizes[i] == 9216) {
                if (found_d == 0) { idm = i; found_d = 1; }
                else idn = i;
            }
        }
    }
    const float* x   = (const float*)d_in[ix];
    const float* eta = (const float*)d_in[ie];
    const float* DM  = (const float*)d_in[idm];
    const float* DN  = (const float*)d_in[idn];
    float* out = (float*)d_out;

    s1_gram_diffs<<<264, 128>>>(x, DM, DN);
    s2_H         <<<128, 128>>>(DM);
    s3_P         <<<128, 128>>>(x, DN, eta);
    s4_out       <<<128, 128>>>(eta, out);
}

// round 7
// speedup vs baseline: 3.4872x; 3.4872x over previous
#include <cuda_runtime.h>

#define MD 96
#define MN 9216

// scratch (device globals; allocation forbidden)
__device__ float g_PT  [32 * MN];   // [t][mm][nn]
__device__ float g_coef[384];       // [0..95]=LMd [96..191]=LMu [192..287]=LNd [288..383]=LNu

__device__ __forceinline__ float wrapf(float v) {
    float r = fmodf(v + 1.0f, 2.0f);
    if (r < 0.0f) r += 2.0f;
    return r - 1.0f;
}

// ---------------------------------------------------------------------------
// KA: blocks 0..127: (t = b>>2, row-strip rs = b&3) -> PT[t][lo..lo+23][0..95]
//     blocks 128,129: tridiagonal Gram coefficients of DM / DN
// ---------------------------------------------------------------------------
__global__ __launch_bounds__(256) void KA(const float* __restrict__ x,
                                          const float* __restrict__ DM,
                                          const float* __restrict__ DN,
                                          const float* __restrict__ eta) {
    // pool layout:
    //  [0..95] dmd | [96..191] dmu | [192..287] dnd | [288..383] dnu
    //  [384..387] corners: cDM94 cDM95 cDN94 cDN95
    //  [388.. ] data region (union):
    //    gram: sD[96*97]
    //    strip: xs[32*116] ; gys[32*87] ; gxs[32*75]
    __shared__ float pool[9700];
    int b = blockIdx.x;
    int tid = threadIdx.x;

    if (b >= 128) {
        // ---- Gram: tridiagonal of D^T D ----
        const float* D = (b - 128) ? DN : DM;
        float* sD = pool + 388;                      // [96][97]
        for (int i = tid; i < MD * MD; i += 256)
            sD[(i / MD) * 97 + (i % MD)] = D[i];
        __syncthreads();
        int base = (b - 128) * 192;
        if (tid < 96) {                              // diag
            float a = 0.f;
            for (int p = 0; p < MD; p++) { float v = sD[p * 97 + tid]; a += v * v; }
            g_coef[base + tid] = a;
        } else if (tid < 191) {                      // superdiag r..r+1, r<95
            int r = tid - 96;
            float a = 0.f;
            for (int p = 0; p < MD; p++) a += sD[p * 97 + r] * sD[p * 97 + r + 1];
            g_coef[base + 96 + r] = a;
        }
        return;
    }

    int t  = b >> 2;
    int rs = b & 3;
    int lo = rs * 24;                                // mm strip [lo, lo+23]
    int rb = (lo > 0) ? lo - 1 : 0;                  // x/Gy row base
    int rt = (lo + 24 < 95) ? lo + 24 : 95;          // last x row
    int pmax = (lo + 23 < 95) ? lo + 23 : 95;        // last Gy row (95 only rs=3)
    int nrow = rt - rb + 1;                          // <= 26
    int pcnt = pmax - rb + 1;                        // 24 or 25

    float* dmd = pool;
    float* dmu = pool + 96;
    float* dnd = pool + 192;
    float* dnu = pool + 288;
    float* cor = pool + 384;
    float* xs  = pool + 388;                         // [s][c4][r-rb]  s*116 + c*29 + ri
    float* gys = xs  + 32 * 116;                     // [s][e][p-rb]   s*87  + e*29 + pi
    float* gxs = gys + 32 * 87;                      // [s][e][mm-lo]  s*75  + e*25 + mi

    // coefficients
    if (tid < 96) {
        dmd[tid] = DM[tid * 97];
        dmu[tid] = (tid < 95) ? DM[tid * 97 + 1] : 0.f;
        dnd[tid] = DN[tid * 97];
        dnu[tid] = (tid < 95) ? DN[tid * 97 + 1] : 0.f;
    } else if (tid == 96) {
        cor[0] = DM[95 * MD + 94];
        cor[1] = DM[95 * MD + 95];
        cor[2] = DN[95 * MD + 94];
        cor[3] = DN[95 * MD + 95];
    }

    // load x[s][rb..rt][3t .. 3t+3]
    for (int idx = tid; idx < 32 * 4 * 26; idx += 256) {
        int s  = idx / 104;
        int rm = idx - s * 104;
        int c  = rm / 26;
        int ri = rm - c * 26;
        int col = 3 * t + c;
        if (ri < nrow && col < MD)
            xs[s * 116 + c * 29 + ri] = x[s * MN + (rb + ri) * MD + col];
    }
    __syncthreads();

    // Gy columns: gys[s][e][p-rb] = wrap(DM-row-p stencil on x col 3t+e)
    for (int idx = tid; idx < 32 * 3 * 25; idx += 256) {
        int s  = idx / 75;
        int rm = idx - s * 75;
        int e  = rm / 25;
        int pi = rm - e * 25;
        int p  = rb + pi;
        if (p <= pmax) {
            const float* xc = xs + s * 116 + e * 29;
            float v;
            if (p < 95) v = dmd[p] * xc[pi] + dmu[p] * xc[pi + 1];
            else        v = cor[0] * xc[94 - rb] + cor[1] * xc[95 - rb];
            gys[s * 87 + e * 29 + pi] = wrapf(v);
        }
    }
    // Gx columns: gxs[s][e][mm-lo] = wrap(x[s][mm][c]*dnd[c] + x[s][mm][c+1]*dnu[c]), c=3t+e
    for (int idx = tid; idx < 32 * 3 * 24; idx += 256) {
        int s  = idx / 72;
        int rm = idx - s * 72;
        int e  = rm / 24;
        int mi = rm - e * 24;
        int ri = lo + mi - rb;
        int c  = 3 * t + e;
        const float* xr = xs + s * 116;
        float v;
        if (c < 95) v = dnd[c] * xr[e * 29 + ri] + dnu[c] * xr[(e + 1) * 29 + ri];
        else        v = cor[2] * xr[1 * 29 + ri] + cor[3] * xr[2 * 29 + ri];  // t=31 only
        gxs[s * 75 + e * 25 + mi] = wrapf(v);
    }
    __syncthreads();

    float ev = eta[0];
    int s2 = 4 * (t & 7) + (t >> 3);

    // PT[t][mm][nn] = H-gather + DN^T-Gx-gather + eta*x[s2][mm][nn]
    for (int idx = tid; idx < 24 * MD; idx += 256) {
        int mm = lo + idx / MD;
        int nn = idx % MD;

        // H term: column mm of DM applied to Gy col (s_h, e_h)
        int sh = nn & 31, eh = nn >> 5;
        const float* gy = gys + sh * 87 + eh * 29;
        float h = 0.f;
        if (mm >= 1)  h += dmu[mm - 1] * gy[mm - 1 - rb];
        if (mm < 95)  h += dmd[mm] * gy[mm - rb];
        if (mm == 94) h += cor[0] * gy[95 - rb];
        if (mm == 95) h += cor[1] * gy[95 - rb];

        // DN^T term: column nn of DN applied across q -> Gx(s_q, e_q) at row mm
        int ml = mm - lo;
        float t2 = 0.f;
        if (nn >= 1) {
            int q = nn - 1;
            t2 += dnu[q] * gxs[(q & 31) * 75 + (q >> 5) * 25 + ml];
        }
        if (nn < 95)  t2 += dnd[nn] * gxs[(nn & 31) * 75 + (nn >> 5) * 25 + ml];
        if (nn == 94) t2 += cor[2] * gxs[31 * 75 + 2 * 25 + ml];
        if (nn == 95) t2 += cor[3] * gxs[31 * 75 + 2 * 25 + ml];

        g_PT[t * MN + mm * MD + nn] = h + t2 + ev * x[s2 * MN + mm * MD + nn];
    }
}

// ---------------------------------------------------------------------------
// KB: out[s2] = LM@PT + PT@LN + eta*PT   (LM, LN exactly tridiagonal)
// grid 128 = (s2 = b>>2, row-strip rs = b&3)
// ---------------------------------------------------------------------------
__global__ __launch_bounds__(256) void KB(const float* __restrict__ eta,
                                          float* __restrict__ out) {
    __shared__ float pts[26 * 97];
    __shared__ float Ld[96], Lu[96], Nd[96], Nu[96];
    int b = blockIdx.x;
    int tid = threadIdx.x;
    int s2 = b >> 2, rs = b & 3;
    int t  = 8 * (s2 & 3) + (s2 >> 2);
    int lo = rs * 24;
    int rb = (lo > 0) ? lo - 1 : 0;
    int rt = (lo + 24 < 95) ? lo + 24 : 95;
    int nrow = rt - rb + 1;

    if (tid < 96) {
        Ld[tid] = g_coef[tid];
        Lu[tid] = g_coef[96 + tid];
        Nd[tid] = g_coef[192 + tid];
        Nu[tid] = g_coef[288 + tid];
    }
    // load PT rows [rb..rt] (coalesced float4)
    for (int idx = tid; idx < 26 * 24; idx += 256) {
        int ri = idx / 24, j4 = idx % 24;
        if (ri < nrow) {
            float4 v = *(const float4*)(g_PT + t * MN + (rb + ri) * MD + 4 * j4);
            pts[ri * 97 + 4 * j4 + 0] = v.x;
            pts[ri * 97 + 4 * j4 + 1] = v.y;
            pts[ri * 97 + 4 * j4 + 2] = v.z;
            pts[ri * 97 + 4 * j4 + 3] = v.w;
        }
    }
    __syncthreads();

    float ev = eta[0];
    for (int idx = tid; idx < 24 * MD; idx += 256) {
        int mi = lo + idx / MD;
        int ni = idx % MD;
        int row = mi - rb;
        float c = pts[row * 97 + ni];
        float v = (Ld[mi] + Nd[ni] + ev) * c;
        if (mi > 0)  v += Lu[mi - 1] * pts[(row - 1) * 97 + ni];
        if (mi < 95) v += Lu[mi]     * pts[(row + 1) * 97 + ni];
        if (ni > 0)  v += Nu[ni - 1] * pts[row * 97 + ni - 1];
        if (ni < 95) v += Nu[ni]     * pts[row * 97 + ni + 1];
        out[s2 * MN + mi * MD + ni] = v;
    }
}

// ---------------------------------------------------------------------------
extern "C" void kernel_launch(void* const* d_in, const int* in_sizes, int n_in,
                              void* d_out, int out_size) {
    // inputs: x(294912), eta(1), A_w(84934656, unused), DM(9216), DN(9216)
    int ix = 0, ie = 1, idm = 3, idn = 4;
    {
        int found_d = 0;
        for (int i = 0; i < n_in; i++) {
            if (in_sizes[i] == 294912) ix = i;
            else if (in_sizes[i] == 1) ie = i;
            else if (in_sizes[i] == 9216) {
                if (found_d == 0) { idm = i; found_d = 1; }
                else idn = i;
            }
        }
    }
    const float* x   = (const float*)d_in[ix];
    const float* eta = (const float*)d_in[ie];
    const float* DM  = (const float*)d_in[idm];
    const float* DN  = (const float*)d_in[idn];
    float* out = (float*)d_out;

    KA<<<130, 256>>>(x, DM, DN, eta);
    KB<<<128, 256>>>(eta, out);
}

// round 11
// speedup vs baseline: 5.0413x; 1.4457x over previous
#include <cuda_runtime.h>

#define MD 96
#define MN 9216

__device__ __forceinline__ float wrapf(float v) {
    float r = fmodf(v + 1.0f, 2.0f);
    if (r < 0.0f) r += 2.0f;
    return r - 1.0f;
}

// ---------------------------------------------------------------------------
// Fully fused: grid 256 = (t = b>>3) x (strip rs = b&7), 12 output rows each.
// Phases (all in smem):
//   1. coefs + x-column staging
//   2. Gy/Gx column diffs (+ tridiagonal Gram coefs)
//   3. PT rows [prb..prt] (includes 1-row halo each side)
//   4. 5-point stencil -> out
// ---------------------------------------------------------------------------
__global__ __launch_bounds__(256) void KF(const float* __restrict__ x,
                                          const float* __restrict__ DM,
                                          const float* __restrict__ DN,
                                          const float* __restrict__ eta,
                                          float* __restrict__ out) {
    __shared__ float dmd[96], dmu[96], dnd[96], dnu[96];
    __shared__ float Ld[96], Lu[96], Nd[96], Nu[96];
    __shared__ float cor[4];
    __shared__ float xs [32 * 4 * 17];   // [(s*4+c)*17 + ri]
    __shared__ float gys[32 * 3 * 16];   // [(s*3+e)*16 + (p - gyb)]
    __shared__ float gxs[32 * 3 * 16];   // [(s*3+e)*16 + (mm - prb)]
    __shared__ float pts[14 * 97];       // [(mm - prb)*97 + nn]

    int b   = blockIdx.x;
    int tid = threadIdx.x;
    int t   = b >> 3;
    int rs  = b & 7;
    int lo  = rs * 12;
    int prb = (lo > 0) ? lo - 1 : 0;
    int prt = (lo + 12 < 95) ? lo + 12 : 95;
    int gyb = (prb > 0) ? prb - 1 : 0;
    int gyt = prt;                        // rs=7: prt=95 covers corner row
    int xb  = gyb;
    int xt  = (gyt + 1 < 95) ? gyt + 1 : 95;
    int nx  = xt - xb + 1;                // <= 16
    int ngy = gyt - gyb + 1;              // <= 15
    int npr = prt - prb + 1;              // <= 14
    int s2  = 4 * (t & 7) + (t >> 3);

    // ---- phase 1: bidiagonal coefs + corners + x columns ----
    if (tid < 96) {
        dmd[tid] = DM[tid * 97];
        dmu[tid] = (tid < 95) ? DM[tid * 97 + 1] : 0.f;
        dnd[tid] = DN[tid * 97];
        dnu[tid] = (tid < 95) ? DN[tid * 97 + 1] : 0.f;
    } else if (tid == 96) {
        cor[0] = DM[95 * MD + 94];
        cor[1] = DM[95 * MD + 95];
        cor[2] = DN[95 * MD + 94];
        cor[3] = DN[95 * MD + 95];
    }
    // x[s][xb+ri][3t+c], c=0..3
    for (int idx = tid; idx < 32 * 4 * 16; idx += 256) {
        int s  = idx >> 6;
        int rm = idx & 63;
        int c  = rm >> 4;
        int ri = rm & 15;
        int col = 3 * t + c;
        if (ri < nx && col < MD)
            xs[(s * 4 + c) * 17 + ri] = x[s * MN + (xb + ri) * MD + col];
    }
    __syncthreads();

    // ---- phase 2: Gy / Gx diffs + Gram tridiagonal coefs ----
    if (tid < 96) {
        int i = tid;
        float a = dmd[i] * dmd[i];
        if (i >= 1)  a += dmu[i - 1] * dmu[i - 1];
        if (i == 94) a += cor[0] * cor[0];
        Ld[i] = a;
        Lu[i] = (i < 95) ? dmd[i] * dmu[i] + ((i == 94) ? cor[0] * cor[1] : 0.f) : 0.f;
        float n = dnd[i] * dnd[i];
        if (i >= 1)  n += dnu[i - 1] * dnu[i - 1];
        if (i == 94) n += cor[2] * cor[2];
        Nd[i] = n;
        Nu[i] = (i < 95) ? dnd[i] * dnu[i] + ((i == 94) ? cor[2] * cor[3] : 0.f) : 0.f;
    }
    for (int idx = tid; idx < 32 * 3 * 16; idx += 256) {
        int u  = idx >> 4;          // s*3+e
        int pi = idx & 15;
        int s  = u / 3, e = u - 3 * s;
        // Gy
        if (pi < ngy) {
            int p = gyb + pi;
            const float* xc = xs + (s * 4 + e) * 17;
            float v;
            if (p < 95) v = dmd[p] * xc[p - xb] + dmu[p] * xc[p - xb + 1];
            else        v = cor[0] * xc[94 - xb] + cor[1] * xc[95 - xb];
            gys[u * 16 + pi] = wrapf(v);
        }
        // Gx
        if (pi < npr) {
            int mm = prb + pi;
            int c  = 3 * t + e;
            int ri = mm - xb;
            float v;
            if (c < 95) v = dnd[c] * xs[(s * 4 + e) * 17 + ri]
                          + dnu[c] * xs[(s * 4 + e + 1) * 17 + ri];
            else        v = cor[2] * xs[(s * 4 + 1) * 17 + ri]
                          + cor[3] * xs[(s * 4 + 2) * 17 + ri];   // t=31, e=2
            gxs[u * 16 + pi] = wrapf(v);
        }
    }
    __syncthreads();

    // ---- phase 3: PT rows [prb..prt] ----
    float ev = eta[0];
    for (int idx = tid; idx < 14 * MD; idx += 256) {
        int rowi = idx / MD;
        int nn   = idx - rowi * MD;
        if (rowi < npr) {
            int mm = prb + rowi;
            // H term: col mm of DM applied to Gy col (nn&31, nn>>5)
            const float* gy = gys + ((nn & 31) * 3 + (nn >> 5)) * 16;
            float h = 0.f;
            if (mm >= 1)  h += dmu[mm - 1] * gy[mm - 1 - gyb];
            if (mm < 95)  h += dmd[mm] * gy[mm - gyb];
            if (mm == 94) h += cor[0] * gy[95 - gyb];
            if (mm == 95) h += cor[1] * gy[95 - gyb];
            // DN^T term: col nn of DN applied across q -> Gx rows
            float t2 = 0.f;
            if (nn >= 1) {
                int q = nn - 1;
                t2 += dnu[q] * gxs[((q & 31) * 3 + (q >> 5)) * 16 + rowi];
            }
            if (nn < 95)  t2 += dnd[nn] * gxs[((nn & 31) * 3 + (nn >> 5)) * 16 + rowi];
            if (nn == 94) t2 += cor[2] * gxs[(31 * 3 + 2) * 16 + rowi];
            if (nn == 95) t2 += cor[3] * gxs[(31 * 3 + 2) * 16 + rowi];
            pts[rowi * 97 + nn] = h + t2 + ev * x[s2 * MN + mm * MD + nn];
        }
    }
    __syncthreads();

    // ---- phase 4: 5-point stencil, coalesced store ----
    for (int idx = tid; idx < 12 * MD; idx += 256) {
        int mi = lo + idx / MD;
        int ni = idx - (idx / MD) * MD;
        int row = mi - prb;
        float c = pts[row * 97 + ni];
        float v = (Ld[mi] + Nd[ni] + ev) * c;
        if (mi > 0)  v += Lu[mi - 1] * pts[(row - 1) * 97 + ni];
        if (mi < 95) v += Lu[mi]     * pts[(row + 1) * 97 + ni];
        if (ni > 0)  v += Nu[ni - 1] * pts[row * 97 + ni - 1];
        if (ni < 95) v += Nu[ni]     * pts[row * 97 + ni + 1];
        out[s2 * MN + mi * MD + ni] = v;
    }
}

// ---------------------------------------------------------------------------
extern "C" void kernel_launch(void* const* d_in, const int* in_sizes, int n_in,
                              void* d_out, int out_size) {
    // inputs: x(294912), eta(1), A_w(84934656, unused), DM(9216), DN(9216)
    int ix = 0, ie = 1, idm = 3, idn = 4;
    {
        int found_d = 0;
        for (int i = 0; i < n_in; i++) {
            if (in_sizes[i] == 294912) ix = i;
            else if (in_sizes[i] == 1) ie = i;
            else if (in_sizes[i] == 9216) {
                if (found_d == 0) { idm = i; found_d = 1; }
                else idn = i;
            }
        }
    }
    const float* x   = (const float*)d_in[ix];
    const float* eta = (const float*)d_in[ie];
    const float* DM  = (const float*)d_in[idm];
    const float* DN  = (const float*)d_in[idn];
    float* out = (float*)d_out;

    KF<<<256, 256>>>(x, DM, DN, eta, out);
}

// round 12
// speedup vs baseline: 5.7975x; 1.1500x over previous
#include <cuda_runtime.h>

#define MD 96
#define MN 9216

__device__ __forceinline__ float wrapf(float v) {
    float r = fmodf(v + 1.0f, 2.0f);
    if (r < 0.0f) r += 2.0f;
    return r - 1.0f;
}

// ---------------------------------------------------------------------------
// Fully fused: grid 512 = (t = b>>4) x (strip rs = b&15), 6 output rows each.
// Phases (all in smem):
//   1. coefs + x-column staging (c-fastest lane order -> 4x fewer sectors)
//   2. Gy/Gx column diffs + tridiagonal Gram coefs
//   3. PT rows [prb..prt] (1-row halo each side)
//   4. 5-point stencil -> out
// ---------------------------------------------------------------------------
__global__ __launch_bounds__(256) void KF(const float* __restrict__ x,
                                          const float* __restrict__ DM,
                                          const float* __restrict__ DN,
                                          const float* __restrict__ eta,
                                          float* __restrict__ out) {
    __shared__ float dmd[96], dmu[96], dnd[96], dnu[96];
    __shared__ float Ld[96], Lu[96], Nd[96], Nu[96];
    __shared__ float cor[4];
    __shared__ float xs [32 * 4 * 11];   // [(s*4+c)*11 + ri]
    __shared__ float gys[32 * 3 * 10];   // [(s*3+e)*10 + (p - gyb)]
    __shared__ float gxs[32 * 3 * 8];    // [(s*3+e)*8  + (mm - prb)]
    __shared__ float pts[8 * 97];        // [(mm - prb)*97 + nn]

    int b   = blockIdx.x;
    int tid = threadIdx.x;
    int t   = b >> 4;
    int rs  = b & 15;
    int lo  = rs * 6;
    int prb = (lo > 0) ? lo - 1 : 0;
    int prt = (lo + 6 < 95) ? lo + 6 : 95;
    int gyb = (prb > 0) ? prb - 1 : 0;
    int gyt = prt;
    int xb  = gyb;
    int xt  = (gyt + 1 < 95) ? gyt + 1 : 95;
    int nx  = xt - xb + 1;                // <= 10
    int ngy = gyt - gyb + 1;              // <= 9
    int npr = prt - prb + 1;              // <= 8
    int s2  = 4 * (t & 7) + (t >> 3);

    // ---- phase 1: bidiagonal coefs + corners + x columns ----
    if (tid < 96) {
        dmd[tid] = DM[tid * 97];
        dmu[tid] = (tid < 95) ? DM[tid * 97 + 1] : 0.f;
        dnd[tid] = DN[tid * 97];
        dnu[tid] = (tid < 95) ? DN[tid * 97 + 1] : 0.f;
    } else if (tid == 96) {
        cor[0] = DM[95 * MD + 94];
        cor[1] = DM[95 * MD + 95];
        cor[2] = DN[95 * MD + 94];
        cor[3] = DN[95 * MD + 95];
    }
    // x[s][xb+ri][3t+c]; lane order: c fastest (4-lane groups hit contiguous 16B)
    for (int idx = tid; idx < 32 * 4 * 10; idx += 256) {
        int c  = idx & 3;
        int rr = idx >> 2;                // 0..319
        int s  = rr / 10;
        int ri = rr - 10 * s;
        int col = 3 * t + c;
        if (ri < nx && col < MD)
            xs[(s * 4 + c) * 11 + ri] = x[s * MN + (xb + ri) * MD + col];
    }
    __syncthreads();

    // ---- phase 2: Gy / Gx diffs + Gram tridiagonal coefs ----
    if (tid < 96) {
        int i = tid;
        float a = dmd[i] * dmd[i];
        if (i >= 1)  a += dmu[i - 1] * dmu[i - 1];
        if (i == 94) a += cor[0] * cor[0];
        Ld[i] = a;
        Lu[i] = (i < 95) ? dmd[i] * dmu[i] + ((i == 94) ? cor[0] * cor[1] : 0.f) : 0.f;
        float n = dnd[i] * dnd[i];
        if (i >= 1)  n += dnu[i - 1] * dnu[i - 1];
        if (i == 94) n += cor[2] * cor[2];
        Nd[i] = n;
        Nu[i] = (i < 95) ? dnd[i] * dnu[i] + ((i == 94) ? cor[2] * cor[3] : 0.f) : 0.f;
    }
    for (int idx = tid; idx < 32 * 3 * 10; idx += 256) {
        int u  = idx / 10;          // s*3+e
        int pi = idx - 10 * u;
        int s  = u / 3, e = u - 3 * s;
        // Gy
        if (pi < ngy) {
            int p = gyb + pi;
            const float* xc = xs + (s * 4 + e) * 11;
            float v;
            if (p < 95) v = dmd[p] * xc[pi] + dmu[p] * xc[pi + 1];
            else        v = cor[0] * xc[94 - xb] + cor[1] * xc[95 - xb];
            gys[u * 10 + pi] = wrapf(v);
        }
        // Gx
        if (pi < npr) {
            int mm = prb + pi;
            int c  = 3 * t + e;
            int ri = mm - xb;
            float v;
            if (c < 95) v = dnd[c] * xs[(s * 4 + e) * 11 + ri]
                          + dnu[c] * xs[(s * 4 + e + 1) * 11 + ri];
            else        v = cor[2] * xs[(s * 4 + 1) * 11 + ri]
                          + cor[3] * xs[(s * 4 + 2) * 11 + ri];   // t=31, e=2
            gxs[u * 8 + pi] = wrapf(v);
        }
    }
    __syncthreads();

    // ---- phase 3: PT rows [prb..prt] ----
    float ev = eta[0];
    for (int idx = tid; idx < 8 * MD; idx += 256) {
        int rowi = idx / MD;
        int nn   = idx - rowi * MD;
        if (rowi < npr) {
            int mm = prb + rowi;
            // H term: col mm of DM applied to Gy col (nn&31, nn>>5)
            const float* gy = gys + ((nn & 31) * 3 + (nn >> 5)) * 10;
            float h = 0.f;
            if (mm >= 1)  h += dmu[mm - 1] * gy[mm - 1 - gyb];
            if (mm < 95)  h += dmd[mm] * gy[mm - gyb];
            if (mm == 94) h += cor[0] * gy[95 - gyb];
            if (mm == 95) h += cor[1] * gy[95 - gyb];
            // DN^T term: col nn of DN across q -> Gx rows
            float t2 = 0.f;
            if (nn >= 1) {
                int q = nn - 1;
                t2 += dnu[q] * gxs[((q & 31) * 3 + (q >> 5)) * 8 + rowi];
            }
            if (nn < 95)  t2 += dnd[nn] * gxs[((nn & 31) * 3 + (nn >> 5)) * 8 + rowi];
            if (nn == 94) t2 += cor[2] * gxs[(31 * 3 + 2) * 8 + rowi];
            if (nn == 95) t2 += cor[3] * gxs[(31 * 3 + 2) * 8 + rowi];
            pts[rowi * 97 + nn] = h + t2 + ev * x[s2 * MN + mm * MD + nn];
        }
    }
    __syncthreads();

    // ---- phase 4: 5-point stencil, coalesced store ----
    for (int idx = tid; idx < 6 * MD; idx += 256) {
        int mi = lo + idx / MD;
        int ni = idx - (idx / MD) * MD;
        int row = mi - prb;
        float c = pts[row * 97 + ni];
        float v = (Ld[mi] + Nd[ni] + ev) * c;
        if (mi > 0)  v += Lu[mi - 1] * pts[(row - 1) * 97 + ni];
        if (mi < 95) v += Lu[mi]     * pts[(row + 1) * 97 + ni];
        if (ni > 0)  v += Nu[ni - 1] * pts[row * 97 + ni - 1];
        if (ni < 95) v += Nu[ni]     * pts[row * 97 + ni + 1];
        out[s2 * MN + mi * MD + ni] = v;
    }
}

// ---------------------------------------------------------------------------
extern "C" void kernel_launch(void* const* d_in, const int* in_sizes, int n_in,
                              void* d_out, int out_size) {
    // inputs: x(294912), eta(1), A_w(84934656, unused), DM(9216), DN(9216)
    int ix = 0, ie = 1, idm = 3, idn = 4;
    {
        int found_d = 0;
        for (int i = 0; i < n_in; i++) {
            if (in_sizes[i] == 294912) ix = i;
            else if (in_sizes[i] == 1) ie = i;
            else if (in_sizes[i] == 9216) {
                if (found_d == 0) { idm = i; found_d = 1; }
                else idn = i;
            }
        }
    }
    const float* x   = (const float*)d_in[ix];
    const float* eta = (const float*)d_in[ie];
    const float* DM  = (const float*)d_in[idm];
    const float* DN  = (const float*)d_in[idn];
    float* out = (float*)d_out;

    KF<<<512, 256>>>(x, DM, DN, eta, out);
}

// round 13
// speedup vs baseline: 5.8120x; 1.0025x over previous
#include <cuda_runtime.h>

#define MD 96
#define MN 9216

__device__ __forceinline__ float wrapf(float v) {
    float r = fmodf(v + 1.0f, 2.0f);
    if (r < 0.0f) r += 2.0f;
    return r - 1.0f;
}

// ---------------------------------------------------------------------------
// Fully fused: grid 1024 = (t = b>>5) x (strip rs = b&31), 3 output rows each.
// Phases (all in smem):
//   1. coefs + x-column staging (c-fastest lanes, shift-only index decode)
//   2. Gy/Gx column diffs + tridiagonal Gram coefs
//   3. PT rows [prb..prt] (1-row halo each side)
//   4. 5-point stencil -> out
// ---------------------------------------------------------------------------
__global__ __launch_bounds__(256) void KF(const float* __restrict__ x,
                                          const float* __restrict__ DM,
                                          const float* __restrict__ DN,
                                          const float* __restrict__ eta,
                                          float* __restrict__ out) {
    __shared__ float dmd[96], dmu[96], dnd[96], dnu[96];
    __shared__ float Ld[96], Lu[96], Nd[96], Nu[96];
    __shared__ float cor[4];
    __shared__ float xs [32 * 4 * 8];    // [(s*4+c)*8 + ri]       1024
    __shared__ float gys[96 * 9];        // [(s*3+e)*9 + (p-gyb)]   864
    __shared__ float gxs[96 * 9];        // [(s*3+e)*9 + (mm-prb)]  864
    __shared__ float pts[5 * 97];        // [(mm-prb)*97 + nn]      485

    int b   = blockIdx.x;
    int tid = threadIdx.x;
    int t   = b >> 5;
    int rs  = b & 31;
    int lo  = rs * 3;
    int prb = (lo > 0) ? lo - 1 : 0;
    int prt = (lo + 3 < 95) ? lo + 3 : 95;
    int gyb = (prb > 0) ? prb - 1 : 0;
    int gyt = prt;
    int xb  = gyb;
    int xt  = (gyt + 1 < 95) ? gyt + 1 : 95;
    int nx  = xt - xb + 1;                // <= 7
    int ngy = gyt - gyb + 1;              // <= 6
    int npr = prt - prb + 1;              // <= 5
    int s2  = 4 * (t & 7) + (t >> 3);

    // ---- phase 1: bidiagonal coefs + corners + x columns ----
    if (tid < 96) {
        dmd[tid] = DM[tid * 97];
        dmu[tid] = (tid < 95) ? DM[tid * 97 + 1] : 0.f;
        dnd[tid] = DN[tid * 97];
        dnu[tid] = (tid < 95) ? DN[tid * 97 + 1] : 0.f;
    } else if (tid == 96) {
        cor[0] = DM[95 * MD + 94];
        cor[1] = DM[95 * MD + 95];
        cor[2] = DN[95 * MD + 94];
        cor[3] = DN[95 * MD + 95];
    }
    // x[s][xb+ri][3t+c]; shift-only decode, c fastest in lane order
#pragma unroll
    for (int k = 0; k < 4; k++) {
        int idx = tid + k * 256;
        int c  = idx & 3;
        int ri = (idx >> 2) & 7;
        int s  = idx >> 5;
        int col = 3 * t + c;
        if (ri < nx && col < MD)
            xs[(s * 4 + c) * 8 + ri] = x[s * MN + (xb + ri) * MD + col];
    }
    __syncthreads();

    // ---- phase 2: Gy / Gx diffs + Gram tridiagonal coefs ----
    if (tid < 96) {
        int i = tid;
        float a = dmd[i] * dmd[i];
        if (i >= 1)  a += dmu[i - 1] * dmu[i - 1];
        if (i == 94) a += cor[0] * cor[0];
        Ld[i] = a;
        Lu[i] = (i < 95) ? dmd[i] * dmu[i] + ((i == 94) ? cor[0] * cor[1] : 0.f) : 0.f;
        float n = dnd[i] * dnd[i];
        if (i >= 1)  n += dnu[i - 1] * dnu[i - 1];
        if (i == 94) n += cor[2] * cor[2];
        Nd[i] = n;
        Nu[i] = (i < 95) ? dnd[i] * dnu[i] + ((i == 94) ? cor[2] * cor[3] : 0.f) : 0.f;
    }
#pragma unroll
    for (int k = 0; k < 3; k++) {
        int idx = tid + k * 256;          // < 768
        int pi = idx & 7;
        int u  = idx >> 3;                // s*3+e, 0..95
        int s  = u / 3;
        int e  = u - 3 * s;
        // Gy (note xb == gyb, so x row index = pi)
        if (pi < ngy) {
            int p = gyb + pi;
            const float* xc = xs + (s * 4 + e) * 8;
            float v;
            if (p < 95) v = dmd[p] * xc[pi] + dmu[p] * xc[pi + 1];
            else        v = cor[0] * xc[94 - xb] + cor[1] * xc[95 - xb];
            gys[u * 9 + pi] = wrapf(v);
        }
        // Gx
        if (pi < npr) {
            int mm = prb + pi;
            int c  = 3 * t + e;
            int ri = mm - xb;
            float v;
            if (c < 95) v = dnd[c] * xs[(s * 4 + e) * 8 + ri]
                          + dnu[c] * xs[(s * 4 + e + 1) * 8 + ri];
            else        v = cor[2] * xs[(s * 4 + 1) * 8 + ri]
                          + cor[3] * xs[(s * 4 + 2) * 8 + ri];   // t=31, e=2
            gxs[u * 9 + pi] = wrapf(v);
        }
    }
    __syncthreads();

    // ---- phase 3: PT rows [prb..prt] ----
    float ev = eta[0];
#pragma unroll
    for (int k = 0; k < 2; k++) {
        int idx = tid + k * 256;          // < 480
        int rowi = idx / MD;
        int nn   = idx - rowi * MD;
        if (rowi < npr) {
            int mm = prb + rowi;
            // H term: col mm of DM applied to Gy col (nn&31, nn>>5)
            const float* gy = gys + ((nn & 31) * 3 + (nn >> 5)) * 9;
            float h = 0.f;
            if (mm >= 1)  h += dmu[mm - 1] * gy[mm - 1 - gyb];
            if (mm < 95)  h += dmd[mm] * gy[mm - gyb];
            if (mm == 94) h += cor[0] * gy[95 - gyb];
            if (mm == 95) h += cor[1] * gy[95 - gyb];
            // DN^T term: col nn of DN across q -> Gx rows
            float t2 = 0.f;
            if (nn >= 1) {
                int q = nn - 1;
                t2 += dnu[q] * gxs[((q & 31) * 3 + (q >> 5)) * 9 + rowi];
            }
            if (nn < 95)  t2 += dnd[nn] * gxs[((nn & 31) * 3 + (nn >> 5)) * 9 + rowi];
            if (nn == 94) t2 += cor[2] * gxs[(31 * 3 + 2) * 9 + rowi];
            if (nn == 95) t2 += cor[3] * gxs[(31 * 3 + 2) * 9 + rowi];
            pts[rowi * 97 + nn] = h + t2 + ev * x[s2 * MN + mm * MD + nn];
        }
    }
    __syncthreads();

    // ---- phase 4: 5-point stencil, coalesced store ----
#pragma unroll
    for (int k = 0; k < 2; k++) {
        int idx = tid + k * 256;          // < 288
        if (idx < 3 * MD) {
            int di = idx / MD;
            int mi = lo + di;
            int ni = idx - di * MD;
            int row = mi - prb;
            float c = pts[row * 97 + ni];
            float v = (Ld[mi] + Nd[ni] + ev) * c;
            if (mi > 0)  v += Lu[mi - 1] * pts[(row - 1) * 97 + ni];
            if (mi < 95) v += Lu[mi]     * pts[(row + 1) * 97 + ni];
            if (ni > 0)  v += Nu[ni - 1] * pts[row * 97 + ni - 1];
            if (ni < 95) v += Nu[ni]     * pts[row * 97 + ni + 1];
            out[s2 * MN + mi * MD + ni] = v;
        }
    }
}

// ---------------------------------------------------------------------------
extern "C" void kernel_launch(void* const* d_in, const int* in_sizes, int n_in,
                              void* d_out, int out_size) {
    // inputs: x(294912), eta(1), A_w(84934656, unused), DM(9216), DN(9216)
    int ix = 0, ie = 1, idm = 3, idn = 4;
    {
        int found_d = 0;
        for (int i = 0; i < n_in; i++) {
            if (in_sizes[i] == 294912) ix = i;
            else if (in_sizes[i] == 1) ie = i;
            else if (in_sizes[i] == 9216) {
                if (found_d == 0) { idm = i; found_d = 1; }
                else idn = i;
            }
        }
    }
    const float* x   = (const float*)d_in[ix];
    const float* eta = (const float*)d_in[ie];
    const float* DM  = (const float*)d_in[idm];
    const float* DN  = (const float*)d_in[idn];
    float* out = (float*)d_out;

    KF<<<1024, 256>>>(x, DM, DN, eta, out);
}